// round 16
// baseline (speedup 1.0000x reference)
#include <cuda_runtime.h>
#include <math.h>

#define F    128
#define TE   64          // edges per block
#define NT   256         // threads per block
#define KS   16          // K-slab for weight staging (double-buffered)
#define HP   132         // padded row stride (floats) for 64xF tiles in smem
#define C0   0.31415926535897931f   // pi / LENGTH(=10)
#define MAXN 10016
#define NSLAB 48         // 8 (layer1) + 5*8 (layer2 chunks)
#define WBUF (2 * KS * F)  // floats per ping-pong buffer (Wa + Wb)

// Scratch for A = inv_node @ phi_W1[:F] + phi_b1   (N x F)
__device__ float g_A[MAXN * F];

typedef unsigned long long ull;

// ---------- f32x2 packed-FMA helpers ----------
static __device__ __forceinline__ ull pack2(float x) {
    ull r; asm("mov.b64 %0, {%1, %1};" : "=l"(r) : "f"(x)); return r;
}
static __device__ __forceinline__ void ffma2(ull& d, ull a, ull b) {
    asm("fma.rn.f32x2 %0, %1, %2, %0;" : "+l"(d) : "l"(a), "l"(b));
}
static __device__ __forceinline__ float2 unpack2(ull a) {
    float2 r; asm("mov.b64 {%0, %1}, %2;" : "=f"(r.x), "=f"(r.y) : "l"(a)); return r;
}
static __device__ __forceinline__ float silu(float x) { return x / (1.0f + expf(-x)); }

// ---------- Precompute A[n][j] = b1[j] + sum_k node[n][k] * phiW1[k][j] ----------
__global__ void precompA(const float* __restrict__ node, const float* __restrict__ W1,
                         const float* __restrict__ b1, int N) {
    __shared__ float xs[8][F];
    const int r0 = blockIdx.x * 8;
    const int tid = threadIdx.x;  // 128 threads
    for (int i = tid; i < 8 * F; i += 128) {
        int r = i >> 7, c = i & 127;
        xs[r][c] = (r0 + r < N) ? node[(size_t)(r0 + r) * F + c] : 0.f;
    }
    __syncthreads();
    const int j = tid;
    float acc[8];
    float b = b1[j];
#pragma unroll
    for (int i = 0; i < 8; i++) acc[i] = b;
    for (int k = 0; k < F; k++) {
        float w = W1[(size_t)k * F + j];
#pragma unroll
        for (int i = 0; i < 8; i++) acc[i] = fmaf(xs[i][k], w, acc[i]);
    }
#pragma unroll
    for (int i = 0; i < 8; i++)
        if (r0 + i < N) g_A[(size_t)(r0 + i) * F + j] = acc[i];
}

// ---------- cp.async staging ----------
static __device__ __forceinline__ void cpasync16(float* s, const float* g) {
    unsigned sa = (unsigned)__cvta_generic_to_shared(s);
    asm volatile("cp.async.cg.shared.global [%0], [%1], 16;\n" :: "r"(sa), "l"(g));
}

// slab u -> (A source, B source, row stride)
static __device__ __forceinline__ void slab_ptrs(int u,
    const float* phiW1, const float* wW1, const float* phiW2, const float* wW2,
    const float*& A, const float*& B, int& stride)
{
    if (u < 8) {
        A = phiW1 + (size_t)(F + u * KS) * F;
        B = wW1   + (size_t)(u * KS) * F;
        stride = F;
    } else {
        int c = (u - 8) >> 3, s = (u - 8) & 7;
        A = phiW2 + (size_t)(s * KS) * (5 * F) + c * F;
        B = wW2   + (size_t)(s * KS) * (5 * F) + c * F;
        stride = 5 * F;
    }
}

static __device__ __forceinline__ void cp_slab(int u, float* sW, int tid,
    const float* phiW1, const float* wW1, const float* phiW2, const float* wW2)
{
    const float *A, *B; int stride;
    slab_ptrs(u, phiW1, wW1, phiW2, wW2, A, B, stride);
    float* base = sW + (u & 1) * WBUF;
#pragma unroll
    for (int q = 0; q < 2; q++) {
        int t = tid + q * NT;          // t in [0, KS*F/4)
        int k = t >> 5, j4 = t & 31;
        cpasync16(&base[k * F + j4 * 4],          &A[(size_t)k * stride + j4 * 4]);
        cpasync16(&base[KS * F + k * F + j4 * 4], &B[(size_t)k * stride + j4 * 4]);
    }
    asm volatile("cp.async.commit_group;\n" ::: "memory");
}

// ---------- Dual 64x128xKS GEMM slab (conflict-free weight loads) ----------
// Thread tn owns cols [tn*4, tn*4+4) (accs [0..1]) and [64+tn*4, ..) (accs [2..3]).
static __device__ __forceinline__ void dual_gemm_slab(
    const float* __restrict__ x1, const float* __restrict__ x2,
    const ulonglong2* __restrict__ wa, const ulonglong2* __restrict__ wb,
    int tn,
    ull (&A1)[4][4], ull (&A2)[4][4])
{
#pragma unroll
    for (int kp = 0; kp < KS / 2; kp++) {
        const int k = 2 * kp;
        ulonglong2 a0  = wa[k * 32 + tn];
        ulonglong2 a0b = wa[k * 32 + 16 + tn];
        ulonglong2 a1r = wa[(k + 1) * 32 + tn];
        ulonglong2 a1b = wa[(k + 1) * 32 + 16 + tn];
        ulonglong2 b0  = wb[k * 32 + tn];
        ulonglong2 b0b = wb[k * 32 + 16 + tn];
        ulonglong2 b1r = wb[(k + 1) * 32 + tn];
        ulonglong2 b1b = wb[(k + 1) * 32 + 16 + tn];
#pragma unroll
        for (int i = 0; i < 4; i++) {
            float2 h1 = *(const float2*)(x1 + i * HP + k);
            float2 h2 = *(const float2*)(x2 + i * HP + k);
            ull p0 = pack2(h1.x), p1 = pack2(h1.y);
            ull q0 = pack2(h2.x), q1 = pack2(h2.y);
            ffma2(A1[i][0], p0, a0.x);  ffma2(A1[i][1], p0, a0.y);
            ffma2(A1[i][2], p0, a0b.x); ffma2(A1[i][3], p0, a0b.y);
            ffma2(A1[i][0], p1, a1r.x); ffma2(A1[i][1], p1, a1r.y);
            ffma2(A1[i][2], p1, a1b.x); ffma2(A1[i][3], p1, a1b.y);
            ffma2(A2[i][0], q0, b0.x);  ffma2(A2[i][1], q0, b0.y);
            ffma2(A2[i][2], q0, b0b.x); ffma2(A2[i][3], q0, b0b.y);
            ffma2(A2[i][0], q1, b1r.x); ffma2(A2[i][1], q1, b1r.y);
            ffma2(A2[i][2], q1, b1b.x); ffma2(A2[i][3], q1, b1b.y);
        }
    }
}

// ---------- dv epilogue helpers (4-feature groups, 12 floats each) ----------
static __device__ __forceinline__ void dv_init_grp(float* dvp, const float* eqp, float4 m) {
    float4 e0 = ((const float4*)eqp)[0];
    float4 e1 = ((const float4*)eqp)[1];
    float4 e2 = ((const float4*)eqp)[2];
    float4 d0, d1, d2;
    d0.x = m.x * e0.x; d0.y = m.x * e0.y; d0.z = m.x * e0.z; d0.w = m.y * e0.w;
    d1.x = m.y * e1.x; d1.y = m.y * e1.y; d1.z = m.z * e1.z; d1.w = m.z * e1.w;
    d2.x = m.z * e2.x; d2.y = m.w * e2.y; d2.z = m.w * e2.z; d2.w = m.w * e2.w;
    ((float4*)dvp)[0] = d0; ((float4*)dvp)[1] = d1; ((float4*)dvp)[2] = d2;
}

static __device__ __forceinline__ void dv_cross_grp(float* dvp, const float* eqp, float4 m,
                                                    float ax, float ay, float az) {
    float ev[12], dv[12];
    ((float4*)ev)[0] = ((const float4*)eqp)[0];
    ((float4*)ev)[1] = ((const float4*)eqp)[1];
    ((float4*)ev)[2] = ((const float4*)eqp)[2];
    ((float4*)dv)[0] = ((float4*)dvp)[0];
    ((float4*)dv)[1] = ((float4*)dvp)[1];
    ((float4*)dv)[2] = ((float4*)dvp)[2];
    float mm[4] = {m.x, m.y, m.z, m.w};
#pragma unroll
    for (int jj = 0; jj < 4; jj++) {
        float bx = ev[jj * 3], by = ev[jj * 3 + 1], bz = ev[jj * 3 + 2];
        float g = mm[jj];
        dv[jj * 3 + 0] += g * (ay * bz - az * by);
        dv[jj * 3 + 1] += g * (az * bx - ax * bz);
        dv[jj * 3 + 2] += g * (ax * by - ay * bx);
    }
    ((float4*)dvp)[0] = ((float4*)dv)[0];
    ((float4*)dvp)[1] = ((float4*)dv)[1];
    ((float4*)dvp)[2] = ((float4*)dv)[2];
}

static __device__ __forceinline__ void dv_dir_grp(float* dvp, float4 m,
                                                  float ax, float ay, float az) {
    float dv[12];
    ((float4*)dv)[0] = ((float4*)dvp)[0];
    ((float4*)dv)[1] = ((float4*)dvp)[1];
    ((float4*)dv)[2] = ((float4*)dvp)[2];
    float mm[4] = {m.x, m.y, m.z, m.w};
#pragma unroll
    for (int jj = 0; jj < 4; jj++) {
        dv[jj * 3 + 0] += mm[jj] * ax;
        dv[jj * 3 + 1] += mm[jj] * ay;
        dv[jj * 3 + 2] += mm[jj] * az;
    }
    ((float4*)dvp)[0] = ((float4*)dv)[0];
    ((float4*)dvp)[1] = ((float4*)dv)[1];
    ((float4*)dvp)[2] = ((float4*)dv)[2];
}

// smem (floats): DV 24576 | H1+H2 16896 | W(2 bufs) 8192 | misc 448
#define SMEM_FLOATS (TE*F*3 + 2*TE*HP + 2*WBUF + 7*TE)
#define SMEM_BYTES  (SMEM_FLOATS * 4)

__global__ __launch_bounds__(NT, 1)
void edge_kernel(const int* __restrict__ ei,
                 const float* __restrict__ eq,
                 const float* __restrict__ invEdge,
                 const float* __restrict__ dist,
                 const float* __restrict__ edir,
                 const float* __restrict__ phiW1,
                 const float* __restrict__ phiW2, const float* __restrict__ phiB2,
                 const float* __restrict__ wW1,  const float* __restrict__ wB1,
                 const float* __restrict__ wW2,  const float* __restrict__ wB2,
                 float* __restrict__ outEq, float* __restrict__ outNode, float* __restrict__ outEdge,
                 int E)
{
    extern __shared__ __align__(16) float smem[];
    float* sDV = smem;                       // TE*F*3  (aliases sX1/sX2 during layer-1)
    float* sX1 = smem;                       // TE*HP
    float* sX2 = smem + TE * HP;             // TE*HP
    float* sH1 = smem + TE * F * 3;          // TE*HP
    float* sH2 = sH1 + TE * HP;              // TE*HP
    float* sW  = sH2 + TE * HP;              // 2 * WBUF
    int*   sSrc = (int*)(sW + 2 * WBUF);
    int*   sDst = sSrc + TE;
    float* sDist = (float*)(sDst + TE);
    float* sDir  = sDist + TE;               // TE*3

    const int tid = threadIdx.x;
    const int tn = tid & 15;                 // 16 col-groups
    const int tm = tid >> 4;                 // 16 row-groups of 4 rows
    const int cA = tn * 4;                   // first 4-col group
    const int cB = 64 + tn * 4;              // second 4-col group
    const int e0 = blockIdx.x * TE;

    // prologue: start staging slab 0 immediately
    cp_slab(0, sW, tid, phiW1, wW1, phiW2, wW2);

    // ---- phase 1: per-edge scalars + inv_edge tile ----
    if (tid < TE) {
        int eg = e0 + tid;
        int s = 0, d = 0; float dd = 0.f, dx = 0.f, dy = 0.f, dz = 0.f;
        if (eg < E) {
            s = ei[eg]; d = ei[E + eg]; dd = dist[eg];
            dx = edir[eg * 3]; dy = edir[eg * 3 + 1]; dz = edir[eg * 3 + 2];
        }
        sSrc[tid] = s; sDst[tid] = d; sDist[tid] = dd;
        sDir[tid * 3] = dx; sDir[tid * 3 + 1] = dy; sDir[tid * 3 + 2] = dz;
    }
    for (int t = tid; t < TE * F / 4; t += NT) {
        int e = t >> 5, j4 = t & 31;
        int eg = e0 + e;
        float4 v = make_float4(0.f, 0.f, 0.f, 0.f);
        if (eg < E) v = *(const float4*)&invEdge[(size_t)eg * F + j4 * 4];
        *(float4*)&sX1[e * HP + j4 * 4] = v;
    }
    __syncthreads();

    // ---- positional encoding tile ----
    for (int t = tid; t < TE * F; t += NT) {
        int e = t >> 7, r = t & 127;
        float dd = sDist[e];
        int rr = r & 63;
        float arg = dd * (float)rr * C0;
        sX2[e * HP + r] = (r < 64) ? sinf(arg) : cosf(arg);
    }
    // NOTE: the first pass's s=0 iteration does wait+__syncthreads before any gemm.

    // ---- layer 1: u_phi = X1 @ W1bot ; u_w = PE @ wW1 (dual) ----
    ull a1[4][4], a2[4][4];
#pragma unroll
    for (int i = 0; i < 4; i++)
#pragma unroll
        for (int cc = 0; cc < 4; cc++) { a1[i][cc] = 0ull; a2[i][cc] = 0ull; }

    for (int s = 0; s < 8; s++) {
        const int u = s;
        asm volatile("cp.async.wait_group 0;\n" ::: "memory");
        __syncthreads();
        if (u + 1 < NSLAB) cp_slab(u + 1, sW, tid, phiW1, wW1, phiW2, wW2);
        const float* wbuf = sW + (u & 1) * WBUF;
        dual_gemm_slab(sX1 + tm * 4 * HP + s * KS, sX2 + tm * 4 * HP + s * KS,
                       (const ulonglong2*)wbuf, (const ulonglong2*)(wbuf + KS * F),
                       tn, a1, a2);
    }

    // layer-1 epilogue: h1 = silu(u_phi + A[src]), h2 = silu(u_w + w_b1)
    {
        float4 bA = *(const float4*)&wB1[cA];
        float4 bB = *(const float4*)&wB1[cB];
#pragma unroll
        for (int i = 0; i < 4; i++) {
            int e = tm * 4 + i;
            int src = sSrc[e];
            float4 Aa = *(const float4*)&g_A[(size_t)src * F + cA];
            float4 Ab = *(const float4*)&g_A[(size_t)src * F + cB];
            float2 u10 = unpack2(a1[i][0]), u11 = unpack2(a1[i][1]);
            float2 u12 = unpack2(a1[i][2]), u13 = unpack2(a1[i][3]);
            float2 u20 = unpack2(a2[i][0]), u21 = unpack2(a2[i][1]);
            float2 u22 = unpack2(a2[i][2]), u23 = unpack2(a2[i][3]);
            float4 h1A = make_float4(silu(u10.x + Aa.x), silu(u10.y + Aa.y),
                                     silu(u11.x + Aa.z), silu(u11.y + Aa.w));
            float4 h1B = make_float4(silu(u12.x + Ab.x), silu(u12.y + Ab.y),
                                     silu(u13.x + Ab.z), silu(u13.y + Ab.w));
            float4 h2A = make_float4(silu(u20.x + bA.x), silu(u20.y + bA.y),
                                     silu(u21.x + bA.z), silu(u21.y + bA.w));
            float4 h2B = make_float4(silu(u22.x + bB.x), silu(u22.y + bB.y),
                                     silu(u23.x + bB.z), silu(u23.y + bB.w));
            *(float4*)&sH1[e * HP + cA] = h1A;
            *(float4*)&sH1[e * HP + cB] = h1B;
            *(float4*)&sH2[e * HP + cA] = h2A;
            *(float4*)&sH2[e * HP + cB] = h2B;
        }
    }

    // ---- layer 2: 5 gate chunks of 128 cols; m = (H1@phiW2+b) * (H2@wW2+b) ----
    for (int c = 0; c < 5; c++) {
        ull aP[4][4], aW[4][4];
#pragma unroll
        for (int i = 0; i < 4; i++)
#pragma unroll
            for (int cc = 0; cc < 4; cc++) { aP[i][cc] = 0ull; aW[i][cc] = 0ull; }

        for (int s = 0; s < 8; s++) {
            const int u = 8 + c * 8 + s;
            asm volatile("cp.async.wait_group 0;\n" ::: "memory");
            __syncthreads();
            if (u + 1 < NSLAB) cp_slab(u + 1, sW, tid, phiW1, wW1, phiW2, wW2);
            const float* wbuf = sW + (u & 1) * WBUF;
            dual_gemm_slab(sH1 + tm * 4 * HP + s * KS, sH2 + tm * 4 * HP + s * KS,
                           (const ulonglong2*)wbuf, (const ulonglong2*)(wbuf + KS * F),
                           tn, aP, aW);
        }

        const int cb = c * F;
        float4 bpA = *(const float4*)&phiB2[cb + cA];
        float4 bpB = *(const float4*)&phiB2[cb + cB];
        float4 bqA = *(const float4*)&wB2[cb + cA];
        float4 bqB = *(const float4*)&wB2[cb + cB];

#pragma unroll
        for (int i = 0; i < 4; i++) {
            int e = tm * 4 + i;
            int eg = e0 + e;
            float2 p0 = unpack2(aP[i][0]), p1 = unpack2(aP[i][1]);
            float2 p2 = unpack2(aP[i][2]), p3 = unpack2(aP[i][3]);
            float2 w0 = unpack2(aW[i][0]), w1 = unpack2(aW[i][1]);
            float2 w2 = unpack2(aW[i][2]), w3 = unpack2(aW[i][3]);
            float4 mA = make_float4((p0.x + bpA.x) * (w0.x + bqA.x),
                                    (p0.y + bpA.y) * (w0.y + bqA.y),
                                    (p1.x + bpA.z) * (w1.x + bqA.z),
                                    (p1.y + bpA.w) * (w1.y + bqA.w));
            float4 mB = make_float4((p2.x + bpB.x) * (w2.x + bqB.x),
                                    (p2.y + bpB.y) * (w2.y + bqB.y),
                                    (p3.x + bpB.z) * (w3.x + bqB.z),
                                    (p3.y + bpB.w) * (w3.y + bqB.w));
            float* dvA = &sDV[(e * F + cA) * 3];
            float* dvB = &sDV[(e * F + cB) * 3];

            if (c == 0) {            // gates * eq[src]  (init dv)
                int src = sSrc[e];
                dv_init_grp(dvA, &eq[(size_t)(src * F + cA) * 3], mA);
                dv_init_grp(dvB, &eq[(size_t)(src * F + cB) * 3], mB);
            } else if (c == 1) {     // cp_gates * cross(edir, eq[dst])
                int dst = sDst[e];
                float ax = sDir[e * 3], ay = sDir[e * 3 + 1], az = sDir[e * 3 + 2];
                dv_cross_grp(dvA, &eq[(size_t)(dst * F + cA) * 3], mA, ax, ay, az);
                dv_cross_grp(dvB, &eq[(size_t)(dst * F + cB) * 3], mB, ax, ay, az);
            } else if (c == 2) {     // scale * edir
                float ax = sDir[e * 3], ay = sDir[e * 3 + 1], az = sDir[e * 3 + 2];
                dv_dir_grp(dvA, mA, ax, ay, az);
                dv_dir_grp(dvB, mB, ax, ay, az);
            } else if (c == 3) {     // ds -> segment sum to outNode
                if (eg < E) {
                    float* base = outNode + (size_t)sDst[e] * F;
                    atomicAdd(base + cA + 0, mA.x); atomicAdd(base + cA + 1, mA.y);
                    atomicAdd(base + cA + 2, mA.z); atomicAdd(base + cA + 3, mA.w);
                    atomicAdd(base + cB + 0, mB.x); atomicAdd(base + cB + 1, mB.y);
                    atomicAdd(base + cB + 2, mB.z); atomicAdd(base + cB + 3, mB.w);
                }
            } else {                 // de -> outEdge = invEdge + de
                if (eg < E) {
                    float4 iA = *(const float4*)&invEdge[(size_t)eg * F + cA];
                    float4 iB = *(const float4*)&invEdge[(size_t)eg * F + cB];
                    float4 oA = make_float4(iA.x + mA.x, iA.y + mA.y, iA.z + mA.z, iA.w + mA.w);
                    float4 oB = make_float4(iB.x + mB.x, iB.y + mB.y, iB.z + mB.z, iB.w + mB.w);
                    *(float4*)&outEdge[(size_t)eg * F + cA] = oA;
                    *(float4*)&outEdge[(size_t)eg * F + cB] = oB;
                }
            }
        }
    }

    // ---- flush dv -> outEq via coalesced atomics ----
    __syncthreads();
    for (int t = tid; t < TE * F * 3; t += NT) {
        int e = t / (F * 3);
        int r = t - e * (F * 3);
        if (e0 + e < E) atomicAdd(&outEq[(size_t)sDst[e] * (F * 3) + r], sDV[t]);
    }
}

extern "C" void kernel_launch(void* const* d_in, const int* in_sizes, int n_in,
                              void* d_out, int out_size) {
    const int*   ei      = (const int*)d_in[0];
    const float* invNode = (const float*)d_in[1];
    const float* eq      = (const float*)d_in[2];
    const float* invEdge = (const float*)d_in[3];
    const float* dist    = (const float*)d_in[4];
    const float* edir    = (const float*)d_in[5];
    const float* phiW1   = (const float*)d_in[6];
    const float* phiB1   = (const float*)d_in[7];
    const float* phiW2   = (const float*)d_in[8];
    const float* phiB2   = (const float*)d_in[9];
    const float* wW1     = (const float*)d_in[10];
    const float* wB1     = (const float*)d_in[11];
    const float* wW2     = (const float*)d_in[12];
    const float* wB2     = (const float*)d_in[13];

    const int E = in_sizes[0] / 2;
    const int N = in_sizes[1] / F;

    float* outEq   = (float*)d_out;
    float* outNode = outEq + (size_t)N * F * 3;
    float* outEdge = outNode + (size_t)N * F;

    // initialize node outputs with base values (edge output fully overwritten)
    cudaMemcpyAsync(outEq, eq, (size_t)N * F * 3 * sizeof(float),
                    cudaMemcpyDeviceToDevice, 0);
    cudaMemcpyAsync(outNode, invNode, (size_t)N * F * sizeof(float),
                    cudaMemcpyDeviceToDevice, 0);

    // A = inv_node @ phiW1_top + phi_b1
    precompA<<<(N + 7) / 8, 128, 0, 0>>>(invNode, phiW1, phiB1, N);

    cudaFuncSetAttribute(edge_kernel, cudaFuncAttributeMaxDynamicSharedMemorySize, SMEM_BYTES);
    const int nb = (E + TE - 1) / TE;
    edge_kernel<<<nb, NT, SMEM_BYTES, 0>>>(ei, eq, invEdge, dist, edir,
                                           phiW1, phiW2, phiB2,
                                           wW1, wB1, wW2, wB2,
                                           outEq, outNode, outEdge, E);
}

// round 17
// speedup vs baseline: 1.0580x; 1.0580x over previous
#include <cuda_runtime.h>
#include <math.h>

#define F    128
#define TE   32          // edges per block
#define NT   128         // threads per block
#define KS   8           // K-slab for weight staging (triple-buffered ring)
#define HP   128         // row stride (floats) for edge tiles in smem
#define C0   0.31415926535897931f   // pi / LENGTH(=10)
#define MAXN 10016
#define NSLAB 96         // 16 (layer1) + 5*16 (layer2 chunks)
#define WBUF (2 * KS * F)  // floats per ring buffer (Wa + Wb) = 2048

// Scratch for A = inv_node @ phi_W1[:F] + phi_b1   (N x F)
__device__ float g_A[MAXN * F];

typedef unsigned long long ull;

// ---------- f32x2 packed-FMA helpers ----------
static __device__ __forceinline__ ull pack2(float x) {
    ull r; asm("mov.b64 %0, {%1, %1};" : "=l"(r) : "f"(x)); return r;
}
static __device__ __forceinline__ void ffma2(ull& d, ull a, ull b) {
    asm("fma.rn.f32x2 %0, %1, %2, %0;" : "+l"(d) : "l"(a), "l"(b));
}
static __device__ __forceinline__ float2 unpack2(ull a) {
    float2 r; asm("mov.b64 {%0, %1}, %2;" : "=f"(r.x), "=f"(r.y) : "l"(a)); return r;
}
static __device__ __forceinline__ float silu(float x) { return x / (1.0f + __expf(-x)); }

// ---------- Precompute A[n][j] = b1[j] + sum_k node[n][k] * phiW1[k][j] ----------
__global__ void precompA(const float* __restrict__ node, const float* __restrict__ W1,
                         const float* __restrict__ b1, int N) {
    __shared__ float xs[8][F];
    const int r0 = blockIdx.x * 8;
    const int tid = threadIdx.x;  // 128 threads
    for (int i = tid; i < 8 * F; i += 128) {
        int r = i >> 7, c = i & 127;
        xs[r][c] = (r0 + r < N) ? node[(size_t)(r0 + r) * F + c] : 0.f;
    }
    __syncthreads();
    const int j = tid;
    float acc[8];
    float b = b1[j];
#pragma unroll
    for (int i = 0; i < 8; i++) acc[i] = b;
    for (int k = 0; k < F; k++) {
        float w = W1[(size_t)k * F + j];
#pragma unroll
        for (int i = 0; i < 8; i++) acc[i] = fmaf(xs[i][k], w, acc[i]);
    }
#pragma unroll
    for (int i = 0; i < 8; i++)
        if (r0 + i < N) g_A[(size_t)(r0 + i) * F + j] = acc[i];
}

// ---------- cp.async staging ----------
static __device__ __forceinline__ void cpasync16(float* s, const float* g) {
    unsigned sa = (unsigned)__cvta_generic_to_shared(s);
    asm volatile("cp.async.cg.shared.global [%0], [%1], 16;\n" :: "r"(sa), "l"(g));
}

// slab u -> (A source, B source, row stride)
static __device__ __forceinline__ void slab_ptrs(int u,
    const float* phiW1, const float* wW1, const float* phiW2, const float* wW2,
    const float*& A, const float*& B, int& stride)
{
    if (u < 16) {
        A = phiW1 + (size_t)(F + u * KS) * F;
        B = wW1   + (size_t)(u * KS) * F;
        stride = F;
    } else {
        int c = (u - 16) >> 4, s = (u - 16) & 15;
        A = phiW2 + (size_t)(s * KS) * (5 * F) + c * F;
        B = wW2   + (size_t)(s * KS) * (5 * F) + c * F;
        stride = 5 * F;
    }
}

static __device__ __forceinline__ void cp_slab(int u, float* sW, int tid,
    const float* phiW1, const float* wW1, const float* phiW2, const float* wW2)
{
    const float *A, *B; int stride;
    slab_ptrs(u, phiW1, wW1, phiW2, wW2, A, B, stride);
    float* base = sW + (u % 3) * WBUF;
#pragma unroll
    for (int q = 0; q < 2; q++) {
        int t = tid + q * NT;          // t in [0, KS*F/4)
        int k = t >> 5, j4 = t & 31;
        cpasync16(&base[k * F + j4 * 4],          &A[(size_t)k * stride + j4 * 4]);
        cpasync16(&base[KS * F + k * F + j4 * 4], &B[(size_t)k * stride + j4 * 4]);
    }
    asm volatile("cp.async.commit_group;\n" ::: "memory");
}

// ---------- Dual 32x128xKS GEMM slab ----------
// Thread tn owns cols [tn*4, tn*4+4) (accs [0..1]) and [64+tn*4, ..) (accs [2..3]).
// Rows: tm*4 .. tm*4+3.  x loads are float4 (4 k-values at once, broadcast).
static __device__ __forceinline__ void dual_gemm_slab(
    const float* __restrict__ x1, const float* __restrict__ x2,
    const ulonglong2* __restrict__ wa, const ulonglong2* __restrict__ wb,
    int tn,
    ull (&A1)[4][4], ull (&A2)[4][4])
{
#pragma unroll
    for (int kq = 0; kq < KS / 4; kq++) {
        const int k = 4 * kq;
        float4 xa[4], xb[4];
#pragma unroll
        for (int i = 0; i < 4; i++) {
            xa[i] = *(const float4*)(x1 + i * HP + k);
            xb[i] = *(const float4*)(x2 + i * HP + k);
        }
#pragma unroll
        for (int kk = 0; kk < 2; kk++) {
            const int k2 = k + 2 * kk;
            ulonglong2 a0  = wa[k2 * 32 + tn];
            ulonglong2 a0b = wa[k2 * 32 + 16 + tn];
            ulonglong2 a1r = wa[(k2 + 1) * 32 + tn];
            ulonglong2 a1b = wa[(k2 + 1) * 32 + 16 + tn];
            ulonglong2 b0  = wb[k2 * 32 + tn];
            ulonglong2 b0b = wb[k2 * 32 + 16 + tn];
            ulonglong2 b1r = wb[(k2 + 1) * 32 + tn];
            ulonglong2 b1b = wb[(k2 + 1) * 32 + 16 + tn];
#pragma unroll
            for (int i = 0; i < 4; i++) {
                float h1lo = kk ? xa[i].z : xa[i].x;
                float h1hi = kk ? xa[i].w : xa[i].y;
                float h2lo = kk ? xb[i].z : xb[i].x;
                float h2hi = kk ? xb[i].w : xb[i].y;
                ull p0 = pack2(h1lo), p1 = pack2(h1hi);
                ull q0 = pack2(h2lo), q1 = pack2(h2hi);
                ffma2(A1[i][0], p0, a0.x);  ffma2(A1[i][1], p0, a0.y);
                ffma2(A1[i][2], p0, a0b.x); ffma2(A1[i][3], p0, a0b.y);
                ffma2(A1[i][0], p1, a1r.x); ffma2(A1[i][1], p1, a1r.y);
                ffma2(A1[i][2], p1, a1b.x); ffma2(A1[i][3], p1, a1b.y);
                ffma2(A2[i][0], q0, b0.x);  ffma2(A2[i][1], q0, b0.y);
                ffma2(A2[i][2], q0, b0b.x); ffma2(A2[i][3], q0, b0b.y);
                ffma2(A2[i][0], q1, b1r.x); ffma2(A2[i][1], q1, b1r.y);
                ffma2(A2[i][2], q1, b1b.x); ffma2(A2[i][3], q1, b1b.y);
            }
        }
    }
}

// ---------- dv epilogue helpers (4-feature groups, 12 floats each) ----------
static __device__ __forceinline__ void dv_init_grp(float* dvp, const float* eqp, float4 m) {
    float4 e0 = ((const float4*)eqp)[0];
    float4 e1 = ((const float4*)eqp)[1];
    float4 e2 = ((const float4*)eqp)[2];
    float4 d0, d1, d2;
    d0.x = m.x * e0.x; d0.y = m.x * e0.y; d0.z = m.x * e0.z; d0.w = m.y * e0.w;
    d1.x = m.y * e1.x; d1.y = m.y * e1.y; d1.z = m.z * e1.z; d1.w = m.z * e1.w;
    d2.x = m.z * e2.x; d2.y = m.w * e2.y; d2.z = m.w * e2.z; d2.w = m.w * e2.w;
    ((float4*)dvp)[0] = d0; ((float4*)dvp)[1] = d1; ((float4*)dvp)[2] = d2;
}

static __device__ __forceinline__ void dv_cross_grp(float* dvp, const float* eqp, float4 m,
                                                    float ax, float ay, float az) {
    float ev[12], dv[12];
    ((float4*)ev)[0] = ((const float4*)eqp)[0];
    ((float4*)ev)[1] = ((const float4*)eqp)[1];
    ((float4*)ev)[2] = ((const float4*)eqp)[2];
    ((float4*)dv)[0] = ((float4*)dvp)[0];
    ((float4*)dv)[1] = ((float4*)dvp)[1];
    ((float4*)dv)[2] = ((float4*)dvp)[2];
    float mm[4] = {m.x, m.y, m.z, m.w};
#pragma unroll
    for (int jj = 0; jj < 4; jj++) {
        float bx = ev[jj * 3], by = ev[jj * 3 + 1], bz = ev[jj * 3 + 2];
        float g = mm[jj];
        dv[jj * 3 + 0] += g * (ay * bz - az * by);
        dv[jj * 3 + 1] += g * (az * bx - ax * bz);
        dv[jj * 3 + 2] += g * (ax * by - ay * bx);
    }
    ((float4*)dvp)[0] = ((float4*)dv)[0];
    ((float4*)dvp)[1] = ((float4*)dv)[1];
    ((float4*)dvp)[2] = ((float4*)dv)[2];
}

static __device__ __forceinline__ void dv_dir_grp(float* dvp, float4 m,
                                                  float ax, float ay, float az) {
    float dv[12];
    ((float4*)dv)[0] = ((float4*)dvp)[0];
    ((float4*)dv)[1] = ((float4*)dvp)[1];
    ((float4*)dv)[2] = ((float4*)dvp)[2];
    float mm[4] = {m.x, m.y, m.z, m.w};
#pragma unroll
    for (int jj = 0; jj < 4; jj++) {
        dv[jj * 3 + 0] += mm[jj] * ax;
        dv[jj * 3 + 1] += mm[jj] * ay;
        dv[jj * 3 + 2] += mm[jj] * az;
    }
    ((float4*)dvp)[0] = ((float4*)dv)[0];
    ((float4*)dvp)[1] = ((float4*)dv)[1];
    ((float4*)dvp)[2] = ((float4*)dv)[2];
}

// smem (floats): DV 12288 (aliases X1/X2 8192) | H1+H2 8192 | W ring 6144 | misc 224
#define SMEM_FLOATS (TE*F*3 + 2*TE*HP + 3*WBUF + 7*TE)
#define SMEM_BYTES  (SMEM_FLOATS * 4)

__global__ __launch_bounds__(NT, 2)
void edge_kernel(const int* __restrict__ ei,
                 const float* __restrict__ eq,
                 const float* __restrict__ invEdge,
                 const float* __restrict__ dist,
                 const float* __restrict__ edir,
                 const float* __restrict__ phiW1,
                 const float* __restrict__ phiW2, const float* __restrict__ phiB2,
                 const float* __restrict__ wW1,  const float* __restrict__ wB1,
                 const float* __restrict__ wW2,  const float* __restrict__ wB2,
                 float* __restrict__ outEq, float* __restrict__ outNode, float* __restrict__ outEdge,
                 int E)
{
    extern __shared__ __align__(16) float smem[];
    float* sDV = smem;                       // TE*F*3  (aliases sX1/sX2 during layer-1)
    float* sX1 = smem;                       // TE*HP
    float* sX2 = smem + TE * HP;             // TE*HP
    float* sH1 = smem + TE * F * 3;          // TE*HP
    float* sH2 = sH1 + TE * HP;              // TE*HP
    float* sW  = sH2 + TE * HP;              // 3 * WBUF
    int*   sSrc = (int*)(sW + 3 * WBUF);
    int*   sDst = sSrc + TE;
    float* sDist = (float*)(sDst + TE);
    float* sDir  = sDist + TE;               // TE*3

    const int tid = threadIdx.x;
    const int tn = tid & 15;                 // 16 col-groups
    const int tm = tid >> 4;                 // 8 row-groups of 4 rows
    const int cA = tn * 4;                   // first 4-col group
    const int cB = 64 + tn * 4;              // second 4-col group
    const int e0 = blockIdx.x * TE;

    // prologue: start staging slabs 0 and 1 immediately (ring has 3 buffers)
    cp_slab(0, sW, tid, phiW1, wW1, phiW2, wW2);
    cp_slab(1, sW, tid, phiW1, wW1, phiW2, wW2);

    // ---- phase 1: per-edge scalars + inv_edge tile ----
    if (tid < TE) {
        int eg = e0 + tid;
        int s = 0, d = 0; float dd = 0.f, dx = 0.f, dy = 0.f, dz = 0.f;
        if (eg < E) {
            s = ei[eg]; d = ei[E + eg]; dd = dist[eg];
            dx = edir[eg * 3]; dy = edir[eg * 3 + 1]; dz = edir[eg * 3 + 2];
        }
        sSrc[tid] = s; sDst[tid] = d; sDist[tid] = dd;
        sDir[tid * 3] = dx; sDir[tid * 3 + 1] = dy; sDir[tid * 3 + 2] = dz;
    }
    for (int t = tid; t < TE * F / 4; t += NT) {
        int e = t >> 5, j4 = t & 31;
        int eg = e0 + e;
        float4 v = make_float4(0.f, 0.f, 0.f, 0.f);
        if (eg < E) v = *(const float4*)&invEdge[(size_t)eg * F + j4 * 4];
        *(float4*)&sX1[e * HP + j4 * 4] = v;
    }
    __syncthreads();

    // ---- positional encoding tile (fast-math sin/cos; budget >> precision loss) ----
    for (int t = tid; t < TE * F; t += NT) {
        int e = t >> 7, r = t & 127;
        float dd = sDist[e];
        int rr = r & 63;
        float arg = dd * (float)rr * C0;
        sX2[e * HP + r] = (r < 64) ? __sinf(arg) : __cosf(arg);
    }
    // first loop iteration's wait+sync orders PE writes before GEMM reads.

    // ---- layer 1: u_phi = X1 @ W1bot ; u_w = PE @ wW1 (dual) ----
    ull a1[4][4], a2[4][4];
#pragma unroll
    for (int i = 0; i < 4; i++)
#pragma unroll
        for (int cc = 0; cc < 4; cc++) { a1[i][cc] = 0ull; a2[i][cc] = 0ull; }

    for (int s = 0; s < 16; s++) {
        const int u = s;
        if (u + 1 >= NSLAB) asm volatile("cp.async.wait_group 0;\n" ::: "memory");
        else                asm volatile("cp.async.wait_group 1;\n" ::: "memory");
        __syncthreads();
        if (u + 2 < NSLAB) cp_slab(u + 2, sW, tid, phiW1, wW1, phiW2, wW2);
        const float* wbuf = sW + (u % 3) * WBUF;
        dual_gemm_slab(sX1 + tm * 4 * HP + s * KS, sX2 + tm * 4 * HP + s * KS,
                       (const ulonglong2*)wbuf, (const ulonglong2*)(wbuf + KS * F),
                       tn, a1, a2);
    }

    // layer-1 epilogue: h1 = silu(u_phi + A[src]), h2 = silu(u_w + w_b1)
    {
        float4 bA = *(const float4*)&wB1[cA];
        float4 bB = *(const float4*)&wB1[cB];
#pragma unroll
        for (int i = 0; i < 4; i++) {
            int e = tm * 4 + i;
            int src = sSrc[e];
            float4 Aa = *(const float4*)&g_A[(size_t)src * F + cA];
            float4 Ab = *(const float4*)&g_A[(size_t)src * F + cB];
            float2 u10 = unpack2(a1[i][0]), u11 = unpack2(a1[i][1]);
            float2 u12 = unpack2(a1[i][2]), u13 = unpack2(a1[i][3]);
            float2 u20 = unpack2(a2[i][0]), u21 = unpack2(a2[i][1]);
            float2 u22 = unpack2(a2[i][2]), u23 = unpack2(a2[i][3]);
            float4 h1A = make_float4(silu(u10.x + Aa.x), silu(u10.y + Aa.y),
                                     silu(u11.x + Aa.z), silu(u11.y + Aa.w));
            float4 h1B = make_float4(silu(u12.x + Ab.x), silu(u12.y + Ab.y),
                                     silu(u13.x + Ab.z), silu(u13.y + Ab.w));
            float4 h2A = make_float4(silu(u20.x + bA.x), silu(u20.y + bA.y),
                                     silu(u21.x + bA.z), silu(u21.y + bA.w));
            float4 h2B = make_float4(silu(u22.x + bB.x), silu(u22.y + bB.y),
                                     silu(u23.x + bB.z), silu(u23.y + bB.w));
            *(float4*)&sH1[e * HP + cA] = h1A;
            *(float4*)&sH1[e * HP + cB] = h1B;
            *(float4*)&sH2[e * HP + cA] = h2A;
            *(float4*)&sH2[e * HP + cB] = h2B;
        }
    }

    // ---- layer 2: 5 gate chunks of 128 cols; m = (H1@phiW2+b) * (H2@wW2+b) ----
    for (int c = 0; c < 5; c++) {
        ull aP[4][4], aW[4][4];
#pragma unroll
        for (int i = 0; i < 4; i++)
#pragma unroll
            for (int cc = 0; cc < 4; cc++) { aP[i][cc] = 0ull; aW[i][cc] = 0ull; }

        for (int s = 0; s < 16; s++) {
            const int u = 16 + c * 16 + s;
            if (u + 1 >= NSLAB) asm volatile("cp.async.wait_group 0;\n" ::: "memory");
            else                asm volatile("cp.async.wait_group 1;\n" ::: "memory");
            __syncthreads();
            if (u + 2 < NSLAB) cp_slab(u + 2, sW, tid, phiW1, wW1, phiW2, wW2);
            const float* wbuf = sW + (u % 3) * WBUF;
            dual_gemm_slab(sH1 + tm * 4 * HP + s * KS, sH2 + tm * 4 * HP + s * KS,
                           (const ulonglong2*)wbuf, (const ulonglong2*)(wbuf + KS * F),
                           tn, aP, aW);
        }

        const int cb = c * F;
        float4 bpA = *(const float4*)&phiB2[cb + cA];
        float4 bpB = *(const float4*)&phiB2[cb + cB];
        float4 bqA = *(const float4*)&wB2[cb + cA];
        float4 bqB = *(const float4*)&wB2[cb + cB];

#pragma unroll
        for (int i = 0; i < 4; i++) {
            int e = tm * 4 + i;
            int eg = e0 + e;
            float2 p0 = unpack2(aP[i][0]), p1 = unpack2(aP[i][1]);
            float2 p2 = unpack2(aP[i][2]), p3 = unpack2(aP[i][3]);
            float2 w0 = unpack2(aW[i][0]), w1 = unpack2(aW[i][1]);
            float2 w2 = unpack2(aW[i][2]), w3 = unpack2(aW[i][3]);
            float4 mA = make_float4((p0.x + bpA.x) * (w0.x + bqA.x),
                                    (p0.y + bpA.y) * (w0.y + bqA.y),
                                    (p1.x + bpA.z) * (w1.x + bqA.z),
                                    (p1.y + bpA.w) * (w1.y + bqA.w));
            float4 mB = make_float4((p2.x + bpB.x) * (w2.x + bqB.x),
                                    (p2.y + bpB.y) * (w2.y + bqB.y),
                                    (p3.x + bpB.z) * (w3.x + bqB.z),
                                    (p3.y + bpB.w) * (w3.y + bqB.w));
            float* dvA = &sDV[(e * F + cA) * 3];
            float* dvB = &sDV[(e * F + cB) * 3];

            if (c == 0) {            // gates * eq[src]  (init dv)
                int src = sSrc[e];
                dv_init_grp(dvA, &eq[(size_t)(src * F + cA) * 3], mA);
                dv_init_grp(dvB, &eq[(size_t)(src * F + cB) * 3], mB);
            } else if (c == 1) {     // cp_gates * cross(edir, eq[dst])
                int dst = sDst[e];
                float ax = sDir[e * 3], ay = sDir[e * 3 + 1], az = sDir[e * 3 + 2];
                dv_cross_grp(dvA, &eq[(size_t)(dst * F + cA) * 3], mA, ax, ay, az);
                dv_cross_grp(dvB, &eq[(size_t)(dst * F + cB) * 3], mB, ax, ay, az);
            } else if (c == 2) {     // scale * edir
                float ax = sDir[e * 3], ay = sDir[e * 3 + 1], az = sDir[e * 3 + 2];
                dv_dir_grp(dvA, mA, ax, ay, az);
                dv_dir_grp(dvB, mB, ax, ay, az);
            } else if (c == 3) {     // ds -> segment sum to outNode
                if (eg < E) {
                    float* base = outNode + (size_t)sDst[e] * F;
                    atomicAdd(base + cA + 0, mA.x); atomicAdd(base + cA + 1, mA.y);
                    atomicAdd(base + cA + 2, mA.z); atomicAdd(base + cA + 3, mA.w);
                    atomicAdd(base + cB + 0, mB.x); atomicAdd(base + cB + 1, mB.y);
                    atomicAdd(base + cB + 2, mB.z); atomicAdd(base + cB + 3, mB.w);
                }
            } else {                 // de -> outEdge = invEdge + de
                if (eg < E) {
                    float4 iA = *(const float4*)&invEdge[(size_t)eg * F + cA];
                    float4 iB = *(const float4*)&invEdge[(size_t)eg * F + cB];
                    float4 oA = make_float4(iA.x + mA.x, iA.y + mA.y, iA.z + mA.z, iA.w + mA.w);
                    float4 oB = make_float4(iB.x + mB.x, iB.y + mB.y, iB.z + mB.z, iB.w + mB.w);
                    *(float4*)&outEdge[(size_t)eg * F + cA] = oA;
                    *(float4*)&outEdge[(size_t)eg * F + cB] = oB;
                }
            }
        }
    }

    // ---- flush dv -> outEq via coalesced atomics ----
    __syncthreads();
    for (int t = tid; t < TE * F * 3; t += NT) {
        int e = t / (F * 3);
        int r = t - e * (F * 3);
        if (e0 + e < E) atomicAdd(&outEq[(size_t)sDst[e] * (F * 3) + r], sDV[t]);
    }
}

extern "C" void kernel_launch(void* const* d_in, const int* in_sizes, int n_in,
                              void* d_out, int out_size) {
    const int*   ei      = (const int*)d_in[0];
    const float* invNode = (const float*)d_in[1];
    const float* eq      = (const float*)d_in[2];
    const float* invEdge = (const float*)d_in[3];
    const float* dist    = (const float*)d_in[4];
    const float* edir    = (const float*)d_in[5];
    const float* phiW1   = (const float*)d_in[6];
    const float* phiB1   = (const float*)d_in[7];
    const float* phiW2   = (const float*)d_in[8];
    const float* phiB2   = (const float*)d_in[9];
    const float* wW1     = (const float*)d_in[10];
    const float* wB1     = (const float*)d_in[11];
    const float* wW2     = (const float*)d_in[12];
    const float* wB2     = (const float*)d_in[13];

    const int E = in_sizes[0] / 2;
    const int N = in_sizes[1] / F;

    float* outEq   = (float*)d_out;
    float* outNode = outEq + (size_t)N * F * 3;
    float* outEdge = outNode + (size_t)N * F;

    // initialize node outputs with base values (edge output fully overwritten)
    cudaMemcpyAsync(outEq, eq, (size_t)N * F * 3 * sizeof(float),
                    cudaMemcpyDeviceToDevice, 0);
    cudaMemcpyAsync(outNode, invNode, (size_t)N * F * sizeof(float),
                    cudaMemcpyDeviceToDevice, 0);

    // A = inv_node @ phiW1_top + phi_b1
    precompA<<<(N + 7) / 8, 128, 0, 0>>>(invNode, phiW1, phiB1, N);

    cudaFuncSetAttribute(edge_kernel, cudaFuncAttributeMaxDynamicSharedMemorySize, SMEM_BYTES);
    const int nb = (E + TE - 1) / TE;
    edge_kernel<<<nb, NT, SMEM_BYTES, 0>>>(ei, eq, invEdge, dist, edir,
                                           phiW1, phiW2, phiB2,
                                           wW1, wB1, wW2, wB2,
                                           outEq, outNode, outEdge, E);
}